// round 8
// baseline (speedup 1.0000x reference)
#include <cuda_runtime.h>

// Analytic bi-Laplacian of f(x) = tanh(x W1^T) W2^T.
//   out[b,o] = sum_h W2[o,h] * (||W1[h,:]||^2)^2 * tanh''''(a_{b,h})
//   tanh''''(u) = 8 t (1 - t^2)(2 - 3 t^2) = t (16 - 40 t^2 + 24 t^4)
//
// Two batch rows per warp. Lane L owns hidden units h = 4L..4L+3, so all
// W1 AND W2 traffic is LDG.128 (32 loads/warp, below the ~55-outstanding
// per-warp cap -> one fully overlapped cold-miss exposure). All loads
// front-batched; 16-accumulator folded shuffle reduction (16 shuffles).

#define B_DIM 256
#define D_DIM 16
#define H_DIM 128
#define O_DIM 8

__device__ __forceinline__ float ex2_approx(float x) {
    float r;
    asm("ex2.approx.f32 %0, %1;" : "=f"(r) : "f"(x));
    return r;
}
__device__ __forceinline__ float rcp_approx(float x) {
    float r;
    asm("rcp.approx.f32 %0, %1;" : "=f"(r) : "f"(x));
    return r;
}

__global__ __launch_bounds__(128, 1) void bilap_kernel(
    const float* __restrict__ x,    // (256, 16)
    const float* __restrict__ W1,   // (128, 16)
    const float* __restrict__ W2,   // (8, 128)
    float* __restrict__ out)        // (256, 8)
{
    const int warp = blockIdx.x * 4 + (threadIdx.x >> 5);
    const int b0   = warp * 2;          // this warp's two batch rows
    const int lane = threadIdx.x & 31;

    // ---------------- load burst: everything, before any FLOP -------------
    const float4* xv0 = reinterpret_cast<const float4*>(x + b0 * D_DIM);
    const float4* xv1 = reinterpret_cast<const float4*>(x + (b0 + 1) * D_DIM);
    const float4 p0 = xv0[0], p1 = xv0[1], p2 = xv0[2], p3 = xv0[3];
    const float4 q0 = xv1[0], q1 = xv1[1], q2 = xv1[2], q3 = xv1[3];

    // W1 rows 4*lane .. 4*lane+3 : 16 consecutive float4s
    float4 w[4][4];  // w[i][j] = W1[4*lane+i][4j..4j+3]
    {
        const float4* w1 = reinterpret_cast<const float4*>(W1 + (4 * lane) * D_DIM);
#pragma unroll
        for (int i = 0; i < 4; i++)
#pragma unroll
            for (int j = 0; j < 4; j++) w[i][j] = w1[i * 4 + j];
    }

    // W2[o][4*lane .. 4*lane+3] : one float4 per output
    float4 w2q[O_DIM];
#pragma unroll
    for (int o = 0; o < O_DIM; o++)
        w2q[o] = *reinterpret_cast<const float4*>(W2 + o * H_DIM + 4 * lane);

    // ---------------- compute --------------------------------------------
    const float LOG2E_X2 = 2.8853900817779268f;  // 2*log2(e)
    float c0v[4], c1v[4];  // per-hidden-unit coefficients, rows 0/1

#pragma unroll
    for (int i = 0; i < 4; i++) {
        const float4 wa = w[i][0], wb = w[i][1], wc = w[i][2], wd = w[i][3];

        // s = ||W1 row||^2 (shared by both batch rows)
        float s0 = wa.x * wa.x, s1 = wc.x * wc.x;
        s0 = fmaf(wa.y, wa.y, s0); s1 = fmaf(wc.y, wc.y, s1);
        s0 = fmaf(wa.z, wa.z, s0); s1 = fmaf(wc.z, wc.z, s1);
        s0 = fmaf(wa.w, wa.w, s0); s1 = fmaf(wc.w, wc.w, s1);
        s0 = fmaf(wb.x, wb.x, s0); s1 = fmaf(wd.x, wd.x, s1);
        s0 = fmaf(wb.y, wb.y, s0); s1 = fmaf(wd.y, wd.y, s1);
        s0 = fmaf(wb.z, wb.z, s0); s1 = fmaf(wd.z, wd.z, s1);
        s0 = fmaf(wb.w, wb.w, s0); s1 = fmaf(wd.w, wd.w, s1);
        const float s  = s0 + s1;
        const float s2 = s * s;

        // pre-activations for both rows, two parallel chains each
        float aA = wa.x * p0.x, aB = wc.x * p2.x;
        float cA = wa.x * q0.x, cB = wc.x * q2.x;
        aA = fmaf(wa.y, p0.y, aA); aB = fmaf(wc.y, p2.y, aB);
        cA = fmaf(wa.y, q0.y, cA); cB = fmaf(wc.y, q2.y, cB);
        aA = fmaf(wa.z, p0.z, aA); aB = fmaf(wc.z, p2.z, aB);
        cA = fmaf(wa.z, q0.z, cA); cB = fmaf(wc.z, q2.z, cB);
        aA = fmaf(wa.w, p0.w, aA); aB = fmaf(wc.w, p2.w, aB);
        cA = fmaf(wa.w, q0.w, cA); cB = fmaf(wc.w, q2.w, cB);
        aA = fmaf(wb.x, p1.x, aA); aB = fmaf(wd.x, p3.x, aB);
        cA = fmaf(wb.x, q1.x, cA); cB = fmaf(wd.x, q3.x, cB);
        aA = fmaf(wb.y, p1.y, aA); aB = fmaf(wd.y, p3.y, aB);
        cA = fmaf(wb.y, q1.y, cA); cB = fmaf(wd.y, q3.y, cB);
        aA = fmaf(wb.z, p1.z, aA); aB = fmaf(wd.z, p3.z, aB);
        cA = fmaf(wb.z, q1.z, cA); cB = fmaf(wd.z, q3.z, cB);
        aA = fmaf(wb.w, p1.w, aA); aB = fmaf(wd.w, p3.w, aB);
        cA = fmaf(wb.w, q1.w, cA); cB = fmaf(wd.w, q3.w, cB);
        const float a_r0 = aA + aB;
        const float a_r1 = cA + cB;

        // t = tanh(a) = 1 - 2/(exp(2a)+1); exact saturation.
        const float e0 = ex2_approx(a_r0 * LOG2E_X2);
        const float e1 = ex2_approx(a_r1 * LOG2E_X2);
        const float t0 = fmaf(-2.f, rcp_approx(e0 + 1.f), 1.f);
        const float t1 = fmaf(-2.f, rcp_approx(e1 + 1.f), 1.f);
        // tanh'''' = t * (16 - 40 u + 24 u^2), u = t^2  (Horner)
        const float u0 = t0 * t0, u1 = t1 * t1;
        float g0 = fmaf(24.f, u0, -40.f); g0 = fmaf(g0, u0, 16.f);
        float g1 = fmaf(24.f, u1, -40.f); g1 = fmaf(g1, u1, 16.f);
        c0v[i] = t0 * g0 * s2;
        c1v[i] = t1 * g1 * s2;
    }

    // accumulate into 16 outputs (row*8 + o)
    float acc[16];
#pragma unroll
    for (int o = 0; o < O_DIM; o++) {
        const float4 wq = w2q[o];
        float a0 = c0v[0] * wq.x, b0r = c1v[0] * wq.x;
        a0  = fmaf(c0v[1], wq.y, a0);  b0r = fmaf(c1v[1], wq.y, b0r);
        a0  = fmaf(c0v[2], wq.z, a0);  b0r = fmaf(c1v[2], wq.z, b0r);
        a0  = fmaf(c0v[3], wq.w, a0);  b0r = fmaf(c1v[3], wq.w, b0r);
        acc[o]     = a0;
        acc[8 + o] = b0r;
    }

    // ---------------- folded reduction: 16 shuffles, depth 5 --------------
    const unsigned FULL = 0xffffffffu;

    float r8[8];
#pragma unroll
    for (int i = 0; i < 8; i++) {           // off=16: 16 -> 8
        float send = (lane & 16) ? acc[i] : acc[i + 8];
        float keep = (lane & 16) ? acc[i + 8] : acc[i];
        r8[i] = keep + __shfl_xor_sync(FULL, send, 16);
    }
    float r4[4];
#pragma unroll
    for (int i = 0; i < 4; i++) {           // off=8: 8 -> 4
        float send = (lane & 8) ? r8[i] : r8[i + 4];
        float keep = (lane & 8) ? r8[i + 4] : r8[i];
        r4[i] = keep + __shfl_xor_sync(FULL, send, 8);
    }
    float r2[2];
#pragma unroll
    for (int i = 0; i < 2; i++) {           // off=4: 4 -> 2
        float send = (lane & 4) ? r4[i] : r4[i + 2];
        float keep = (lane & 4) ? r4[i + 2] : r4[i];
        r2[i] = keep + __shfl_xor_sync(FULL, send, 4);
    }
    {                                       // off=2: 2 -> 1
        float send = (lane & 2) ? r2[0] : r2[1];
        float keep = (lane & 2) ? r2[1] : r2[0];
        r2[0] = keep + __shfl_xor_sync(FULL, send, 2);
    }
    float r = r2[0] + __shfl_xor_sync(FULL, r2[0], 1);  // off=1

    // lane pair (lane>>1) holds index j = bits{4,3,2,1} of lane
    if ((lane & 1) == 0) {
        const int j   = (lane >> 1) & 15;
        const int row = j >> 3;
        const int o   = j & 7;
        out[(b0 + row) * O_DIM + o] = r;
    }
}

extern "C" void kernel_launch(void* const* d_in, const int* in_sizes, int n_in,
                              void* d_out, int out_size) {
    const float* x  = (const float*)d_in[0];   // 256*16
    const float* W1 = (const float*)d_in[1];   // 128*16
    const float* W2 = (const float*)d_in[2];   // 8*128
    float* out = (float*)d_out;                // 256*8
    // 32 blocks x 128 threads = 128 warps x 2 rows = 256 batch rows.
    bilap_kernel<<<32, 128>>>(x, W1, W2, out);
}

// round 9
// speedup vs baseline: 1.0435x; 1.0435x over previous
#include <cuda_runtime.h>

// Analytic bi-Laplacian of f(x) = tanh(x W1^T) W2^T.
//   out[b,o] = sum_h W2[o,h] * (||W1[h,:]||^2)^2 * tanh''''(a_{b,h})
//   tanh''''(u) = t (16 - 40 t^2 + 24 t^4),  t = tanh(u)
//
// R7 memory layout (best measured): lane owns h = lane+32k, W1 float4s at
// 64B lane stride (16 L1 lines per LDG, not 32), W2 via coalesced scalar
// loads. Two batch rows per warp, all loads front-batched, Horner tanh'''',
// 4-way-split dot chains, 16-shuffle folded reduction.

#define B_DIM 256
#define D_DIM 16
#define H_DIM 128
#define O_DIM 8

__device__ __forceinline__ float ex2_approx(float x) {
    float r;
    asm("ex2.approx.f32 %0, %1;" : "=f"(r) : "f"(x));
    return r;
}
__device__ __forceinline__ float rcp_approx(float x) {
    float r;
    asm("rcp.approx.f32 %0, %1;" : "=f"(r) : "f"(x));
    return r;
}

__global__ __launch_bounds__(128, 1) void bilap_kernel(
    const float* __restrict__ x,    // (256, 16)
    const float* __restrict__ W1,   // (128, 16)
    const float* __restrict__ W2,   // (8, 128)
    float* __restrict__ out)        // (256, 8)
{
    const int warp = blockIdx.x * 4 + (threadIdx.x >> 5);
    const int b0   = warp * 2;          // this warp's two batch rows
    const int lane = threadIdx.x & 31;

    // ---------------- load burst: everything, before any FLOP -------------
    const float4* xv0 = reinterpret_cast<const float4*>(x + b0 * D_DIM);
    const float4* xv1 = reinterpret_cast<const float4*>(x + (b0 + 1) * D_DIM);
    const float4 p0 = xv0[0], p1 = xv0[1], p2 = xv0[2], p3 = xv0[3];
    const float4 q0 = xv1[0], q1 = xv1[1], q2 = xv1[2], q3 = xv1[3];

    float4 w[4][4];  // w[k][i] = W1[lane+32k][4i..4i+3]
#pragma unroll
    for (int k = 0; k < 4; k++) {
        const float4* w1 = reinterpret_cast<const float4*>(W1 + (lane + 32 * k) * D_DIM);
#pragma unroll
        for (int i = 0; i < 4; i++) w[k][i] = w1[i];
    }

    float w2v[4][O_DIM];  // W2[o][lane+32k]  (coalesced 128B per (o,k))
#pragma unroll
    for (int k = 0; k < 4; k++)
#pragma unroll
        for (int o = 0; o < O_DIM; o++)
            w2v[k][o] = __ldg(W2 + o * H_DIM + lane + 32 * k);

    // ---------------- compute --------------------------------------------
    const float LOG2E_X2 = 2.8853900817779268f;  // 2*log2(e)
    float acc[16];  // [row*8 + o]
#pragma unroll
    for (int j = 0; j < 16; j++) acc[j] = 0.f;

#pragma unroll
    for (int k = 0; k < 4; k++) {
        const float4 wa = w[k][0], wb = w[k][1], wc = w[k][2], wd = w[k][3];

        // s = ||W1 row||^2 : four parallel 4-deep chains
        float sA = wa.x * wa.x, sB = wb.x * wb.x, sC = wc.x * wc.x, sD = wd.x * wd.x;
        sA = fmaf(wa.y, wa.y, sA); sB = fmaf(wb.y, wb.y, sB);
        sC = fmaf(wc.y, wc.y, sC); sD = fmaf(wd.y, wd.y, sD);
        sA = fmaf(wa.z, wa.z, sA); sB = fmaf(wb.z, wb.z, sB);
        sC = fmaf(wc.z, wc.z, sC); sD = fmaf(wd.z, wd.z, sD);
        sA = fmaf(wa.w, wa.w, sA); sB = fmaf(wb.w, wb.w, sB);
        sC = fmaf(wc.w, wc.w, sC); sD = fmaf(wd.w, wd.w, sD);
        const float s  = (sA + sB) + (sC + sD);
        const float s2 = s * s;

        // a (row 0) and c (row 1): four parallel 4-deep chains each
        float aA = wa.x * p0.x, aB = wb.x * p1.x, aC = wc.x * p2.x, aD = wd.x * p3.x;
        float cA = wa.x * q0.x, cB = wb.x * q1.x, cC = wc.x * q2.x, cD = wd.x * q3.x;
        aA = fmaf(wa.y, p0.y, aA); aB = fmaf(wb.y, p1.y, aB);
        aC = fmaf(wc.y, p2.y, aC); aD = fmaf(wd.y, p3.y, aD);
        cA = fmaf(wa.y, q0.y, cA); cB = fmaf(wb.y, q1.y, cB);
        cC = fmaf(wc.y, q2.y, cC); cD = fmaf(wd.y, q3.y, cD);
        aA = fmaf(wa.z, p0.z, aA); aB = fmaf(wb.z, p1.z, aB);
        aC = fmaf(wc.z, p2.z, aC); aD = fmaf(wd.z, p3.z, aD);
        cA = fmaf(wa.z, q0.z, cA); cB = fmaf(wb.z, q1.z, cB);
        cC = fmaf(wc.z, q2.z, cC); cD = fmaf(wd.z, q3.z, cD);
        aA = fmaf(wa.w, p0.w, aA); aB = fmaf(wb.w, p1.w, aB);
        aC = fmaf(wc.w, p2.w, aC); aD = fmaf(wd.w, p3.w, aD);
        cA = fmaf(wa.w, q0.w, cA); cB = fmaf(wb.w, q1.w, cB);
        cC = fmaf(wc.w, q2.w, cC); cD = fmaf(wd.w, q3.w, cD);
        const float a_r0 = (aA + aB) + (aC + aD);
        const float a_r1 = (cA + cB) + (cC + cD);

        // t = tanh(a) = 1 - 2/(exp(2a)+1); exact saturation.
        const float e0 = ex2_approx(a_r0 * LOG2E_X2);
        const float e1 = ex2_approx(a_r1 * LOG2E_X2);
        const float t0 = fmaf(-2.f, rcp_approx(e0 + 1.f), 1.f);
        const float t1 = fmaf(-2.f, rcp_approx(e1 + 1.f), 1.f);
        // tanh'''' = t * (16 + u*(-40 + 24u)), u = t^2  (Horner)
        const float u0 = t0 * t0, u1 = t1 * t1;
        float g0 = fmaf(24.f, u0, -40.f); g0 = fmaf(g0, u0, 16.f);
        float g1 = fmaf(24.f, u1, -40.f); g1 = fmaf(g1, u1, 16.f);
        const float c0 = t0 * g0 * s2;
        const float c1 = t1 * g1 * s2;

#pragma unroll
        for (int o = 0; o < O_DIM; o++) {
            acc[o]     = fmaf(c0, w2v[k][o], acc[o]);
            acc[8 + o] = fmaf(c1, w2v[k][o], acc[8 + o]);
        }
    }

    // ---------------- folded reduction: 16 shuffles, depth 5 --------------
    const unsigned FULL = 0xffffffffu;

    float r8[8];
#pragma unroll
    for (int i = 0; i < 8; i++) {           // off=16: 16 -> 8
        float send = (lane & 16) ? acc[i] : acc[i + 8];
        float keep = (lane & 16) ? acc[i + 8] : acc[i];
        r8[i] = keep + __shfl_xor_sync(FULL, send, 16);
    }
    float r4[4];
#pragma unroll
    for (int i = 0; i < 4; i++) {           // off=8: 8 -> 4
        float send = (lane & 8) ? r8[i] : r8[i + 4];
        float keep = (lane & 8) ? r8[i + 4] : r8[i];
        r4[i] = keep + __shfl_xor_sync(FULL, send, 8);
    }
    float r2[2];
#pragma unroll
    for (int i = 0; i < 2; i++) {           // off=4: 4 -> 2
        float send = (lane & 4) ? r4[i] : r4[i + 2];
        float keep = (lane & 4) ? r4[i + 2] : r4[i];
        r2[i] = keep + __shfl_xor_sync(FULL, send, 4);
    }
    {                                       // off=2: 2 -> 1
        float send = (lane & 2) ? r2[0] : r2[1];
        float keep = (lane & 2) ? r2[1] : r2[0];
        r2[0] = keep + __shfl_xor_sync(FULL, send, 2);
    }
    float r = r2[0] + __shfl_xor_sync(FULL, r2[0], 1);  // off=1

    // lane pair (lane>>1) holds index j = lane bits {4,3,2,1}
    if ((lane & 1) == 0) {
        const int j   = (lane >> 1) & 15;
        const int row = j >> 3;
        const int o   = j & 7;
        out[(b0 + row) * O_DIM + o] = r;
    }
}

extern "C" void kernel_launch(void* const* d_in, const int* in_sizes, int n_in,
                              void* d_out, int out_size) {
    const float* x  = (const float*)d_in[0];   // 256*16
    const float* W1 = (const float*)d_in[1];   // 128*16
    const float* W2 = (const float*)d_in[2];   // 8*128
    float* out = (float*)d_out;                // 256*8
    // 32 blocks x 128 threads = 128 warps x 2 rows = 256 batch rows.
    bilap_kernel<<<32, 128>>>(x, W1, W2, out);
}